// round 7
// baseline (speedup 1.0000x reference)
#include <cuda_runtime.h>

// CREStereo fused bilinear-warp + 9-tap group correlation.
// left/right: [B,C,H,W] f32, flow: [B,2,H,W] f32
// out: [B, G*9, H, W] f32
// out[b, g*9+o, y, x] = mean_c( left[b,g*64+c,y,x] * warped[b,g*64+c,y,clamp(x+o-4)] )
// warped = bilinear(right, x+fx, y+fy), zero outside image.

#define BB     4
#define CC_T   256
#define HH     128
#define WW     256
#define GG     4
#define CG     64
#define WIN    9
#define CCH    8
#define NCHUNK (CG / CCH)
#define HW     (HH * WW)
#define RPAD   (WW + 8)          // 4 replicate pads each side

__global__ __launch_bounds__(256, 4)
void crestereo_corr_kernel(const float* __restrict__ left,
                           const float* __restrict__ right,
                           const float* __restrict__ flow,
                           float* __restrict__ out)
{
    __shared__ float sh[2][CCH][RPAD];   // double-buffered warped rows, padded

    // bid = ((b*H + y)*G + g): adjacent-y CTAs adjacent -> L2 reuse of right rows
    const int bid = blockIdx.x;
    const int g   = bid & (GG - 1);
    const int by  = bid >> 2;
    const int y   = by & (HH - 1);
    const int b   = by >> 7;

    const int x = threadIdx.x;

    // ---- per-pixel bilinear params (computed once) ----
    const float fx = flow[((b * 2 + 0) * HH + y) * WW + x];
    const float fy = flow[((b * 2 + 1) * HH + y) * WW + x];
    const float sx = (float)x + fx;
    const float sy = (float)y + fy;
    const float x0f = floorf(sx);
    const float y0f = floorf(sy);
    const float axf = sx - x0f;
    const float ayf = sy - y0f;
    const int x0 = (int)x0f, y0 = (int)y0f;
    const int x1 = x0 + 1,   y1 = y0 + 1;

    float w00 = (1.f - axf) * (1.f - ayf);
    float w01 = axf * (1.f - ayf);
    float w10 = (1.f - axf) * ayf;
    float w11 = axf * ayf;

    const bool vx0 = ((unsigned)x0 < (unsigned)WW);
    const bool vx1 = ((unsigned)x1 < (unsigned)WW);
    const bool vy0 = ((unsigned)y0 < (unsigned)HH);
    const bool vy1 = ((unsigned)y1 < (unsigned)HH);
    if (!(vx0 && vy0)) w00 = 0.f;
    if (!(vx1 && vy0)) w01 = 0.f;
    if (!(vx0 && vy1)) w10 = 0.f;
    if (!(vx1 && vy1)) w11 = 0.f;

    const int cx0 = min(max(x0, 0), WW - 1);
    const int cx1 = min(max(x1, 0), WW - 1);
    const int cy0 = min(max(y0, 0), HH - 1);
    const int cy1 = min(max(y1, 0), HH - 1);

    // Paired column loads: aligned float2 at even column e covers {e, e+1}.
    const int  e     = cx0 & ~1;
    const bool odd   = (cx0 & 1) != 0;
    const bool needS = (cx1 != e + 1);    // odd-normal or left-edge clamp
    const int ro0 = cy0 * WW + e;         // 8B-aligned
    const int ro1 = cy1 * WW + e;
    const int so0 = cy0 * WW + cx1;
    const int so1 = cy1 * WW + cx1;

    const float* __restrict__ rbase = right + (size_t)(b * CC_T + g * CG) * HW;
    const float* __restrict__ lbase = left  + (size_t)(b * CC_T + g * CG) * HW
                                            + (size_t)y * WW + x;

    float acc[WIN];
#pragma unroll
    for (int o = 0; o < WIN; o++) acc[o] = 0.f;

    const bool is0   = (x == 0);
    const bool is255 = (x == WW - 1);

    for (int i = 0; i < NCHUNK; i++) {
        const int buf = i & 1;
        float vreg[CCH];

        // ---- gather: this thread's pixel, 8 channels ----
#pragma unroll
        for (int cc = 0; cc < CCH; cc++) {
            const float* __restrict__ rp = rbase + (size_t)(i * CCH + cc) * HW;
            const float2 a0 = *reinterpret_cast<const float2*>(rp + ro0);
            const float2 a1 = *reinterpret_cast<const float2*>(rp + ro1);
            float q0 = 0.f, q1 = 0.f;
            if (needS) { q0 = __ldg(rp + so0); q1 = __ldg(rp + so1); }
            const float v0a = odd   ? a0.y : a0.x;
            const float v1a = needS ? q0   : a0.y;
            const float v0b = odd   ? a1.y : a1.x;
            const float v1b = needS ? q1   : a1.y;
            const float v = w00 * v0a + w01 * v1a + w10 * v0b + w11 * v1b;
            vreg[cc] = v;
            sh[buf][cc][4 + x] = v;
            if (is0) {              // replicate-pad left
                sh[buf][cc][0] = v; sh[buf][cc][1] = v;
                sh[buf][cc][2] = v; sh[buf][cc][3] = v;
            }
            if (is255) {            // replicate-pad right
                sh[buf][cc][260] = v; sh[buf][cc][261] = v;
                sh[buf][cc][262] = v; sh[buf][cc][263] = v;
            }
        }

        // Single barrier per chunk. Safety of the missing second barrier:
        // a warp entering gather(i+1) (writes buf^1) has passed sync(i),
        // which implies every warp finished corr(i-1) — the last reads of
        // buf^1. So no data hazard.
        __syncthreads();

        // ---- corr: same pixel, 8 channels, 9 taps from padded shared ----
#pragma unroll
        for (int cc = 0; cc < CCH; cc++) {
            const float l = lbase[(size_t)(i * CCH + cc) * HW];
            const float* __restrict__ row = sh[buf][cc] + x;  // taps at row[o]
#pragma unroll
            for (int o = 0; o < WIN; o++) {
                const float wv = (o == 4) ? vreg[cc] : row[o];
                acc[o] = fmaf(l, wv, acc[o]);
            }
        }
    }

    const float scale = 1.f / (float)CG;
    float* __restrict__ ob = out + (((size_t)(b * GG + g) * WIN) * HH + y) * WW + x;
#pragma unroll
    for (int o = 0; o < WIN; o++)
        ob[(size_t)o * HW] = acc[o] * scale;
}

extern "C" void kernel_launch(void* const* d_in, const int* in_sizes, int n_in,
                              void* d_out, int out_size)
{
    const float* left  = (const float*)d_in[0];
    const float* right = (const float*)d_in[1];
    const float* flow  = (const float*)d_in[2];
    float* out = (float*)d_out;

    const int grid = BB * HH * GG;   // 2048 CTAs, 256 threads
    crestereo_corr_kernel<<<grid, 256>>>(left, right, flow, out);
}

// round 9
// speedup vs baseline: 1.1203x; 1.1203x over previous
#include <cuda_runtime.h>

// CREStereo fused bilinear-warp + 9-tap group correlation.  (R2 skeleton)
// left/right: [B,C,H,W] f32, flow: [B,2,H,W] f32
// out: [B, G*9, H, W] f32
// out[b, g*9+o, y, x] = mean_c( left[b,g*64+c,y,x] * warped[b,g*64+c,y,clamp(x+o-4)] )
// warped = bilinear(right, x+fx, y+fy), zero outside image.

#define BB   4
#define CC_T 256
#define HH   128
#define WW   256
#define GG   4
#define CG   64
#define WIN  9
#define CCH  8
#define HW   (HH * WW)
#define RPAD (WW + 8)   // 4 replicate pads each side

__global__ __launch_bounds__(WW, 4)
void crestereo_corr_kernel(const float* __restrict__ left,
                           const float* __restrict__ right,
                           const float* __restrict__ flow,
                           float* __restrict__ out)
{
    __shared__ float sh[CCH][RPAD];

    // bid = ((b*H + y)*G + g)
    const int bid = blockIdx.x;
    const int g   = bid & (GG - 1);
    const int by  = bid >> 2;
    const int y   = by & (HH - 1);
    const int b   = by >> 7;

    const int x = threadIdx.x;

    // ---- per-pixel bilinear sampling parameters (computed once) ----
    const float fx = flow[((b * 2 + 0) * HH + y) * WW + x];
    const float fy = flow[((b * 2 + 1) * HH + y) * WW + x];
    const float sx = (float)x + fx;
    const float sy = (float)y + fy;
    const float x0f = floorf(sx);
    const float y0f = floorf(sy);
    const float axf = sx - x0f;
    const float ayf = sy - y0f;
    const int x0 = (int)x0f, y0 = (int)y0f;
    const int x1 = x0 + 1,   y1 = y0 + 1;

    float w00 = (1.f - axf) * (1.f - ayf);
    float w01 = axf * (1.f - ayf);
    float w10 = (1.f - axf) * ayf;
    float w11 = axf * ayf;

    const bool vx0 = ((unsigned)x0 < (unsigned)WW);
    const bool vx1 = ((unsigned)x1 < (unsigned)WW);
    const bool vy0 = ((unsigned)y0 < (unsigned)HH);
    const bool vy1 = ((unsigned)y1 < (unsigned)HH);
    if (!(vx0 && vy0)) w00 = 0.f;
    if (!(vx1 && vy0)) w01 = 0.f;
    if (!(vx0 && vy1)) w10 = 0.f;
    if (!(vx1 && vy1)) w11 = 0.f;

    const int cx0 = min(max(x0, 0), WW - 1);
    const int cx1 = min(max(x1, 0), WW - 1);
    const int cy0 = min(max(y0, 0), HH - 1);
    const int cy1 = min(max(y1, 0), HH - 1);
    const int o00 = cy0 * WW + cx0;
    const int o01 = cy0 * WW + cx1;
    const int o10 = cy1 * WW + cx0;
    const int o11 = cy1 * WW + cx1;

    const float* __restrict__ rbase = right + (size_t)(b * CC_T + g * CG) * HW;
    const float* __restrict__ lbase = left  + (size_t)(b * CC_T + g * CG) * HW
                                            + (size_t)y * WW + x;

    float acc[WIN];
#pragma unroll
    for (int o = 0; o < WIN; o++) acc[o] = 0.f;

    const bool is0   = (x == 0);
    const bool is255 = (x == WW - 1);

    for (int c0 = 0; c0 < CG; c0 += CCH) {
        float vreg[CCH];
        float lv[CCH];

        __syncthreads();   // previous chunk's corr reads complete before overwrite

        // ---- gather: 4 independent scalar loads per channel (max MLP; do not
        //      restructure — every "smarter" gather variant measured slower) ----
#pragma unroll
        for (int cc = 0; cc < CCH; cc++) {
            const float* __restrict__ rp = rbase + (size_t)(c0 + cc) * HW;
            float v = w00 * __ldg(rp + o00) + w01 * __ldg(rp + o01)
                    + w10 * __ldg(rp + o10) + w11 * __ldg(rp + o11);
            vreg[cc]        = v;
            sh[cc][4 + x]   = v;
            if (is0) {              // replicate-pad left edge
                sh[cc][0] = v; sh[cc][1] = v; sh[cc][2] = v; sh[cc][3] = v;
            }
            if (is255) {            // replicate-pad right edge
                sh[cc][260] = v; sh[cc][261] = v; sh[cc][262] = v; sh[cc][263] = v;
            }
        }

        // prefetch left (coalesced, shared-independent): latency hides under barrier
#pragma unroll
        for (int cc = 0; cc < CCH; cc++)
            lv[cc] = lbase[(size_t)(c0 + cc) * HW];

        __syncthreads();

        // ---- corr: 9 taps from padded shared (immediate offsets) ----
#pragma unroll
        for (int cc = 0; cc < CCH; cc++) {
            const float l = lv[cc];
            const float* __restrict__ row = sh[cc] + x;   // taps at row[0..8]
#pragma unroll
            for (int o = 0; o < WIN; o++) {
                const float wv = (o == 4) ? vreg[cc] : row[o];  // center from reg
                acc[o] = fmaf(l, wv, acc[o]);
            }
        }
    }

    const float scale = 1.f / (float)CG;
    float* __restrict__ ob = out + (((size_t)(b * GG + g) * WIN) * HH + y) * WW + x;
#pragma unroll
    for (int o = 0; o < WIN; o++)
        ob[(size_t)o * HW] = acc[o] * scale;
}

extern "C" void kernel_launch(void* const* d_in, const int* in_sizes, int n_in,
                              void* d_out, int out_size)
{
    const float* left  = (const float*)d_in[0];
    const float* right = (const float*)d_in[1];
    const float* flow  = (const float*)d_in[2];
    float* out = (float*)d_out;

    const int grid = BB * HH * GG;   // 2048 CTAs, 256 threads
    crestereo_corr_kernel<<<grid, WW>>>(left, right, flow, out);
}

// round 10
// speedup vs baseline: 1.6547x; 1.4771x over previous
#include <cuda_runtime.h>

// CREStereo fused bilinear-warp + 9-tap group correlation.
// EXACT R2 structure (best measured: 109.3us). Only deltas: __ldcs on the
// read-once left stream, __stcs on the write-once output stream. Nothing
// else — the 4-scalar-ldg gather batch and its register budget are the
// performance-critical invariant (MLP of the scattered loads).
//
// left:  [B, C, H, W] f32
// right: [B, C, H, W] f32
// flow:  [B, 2, H, W] f32
// out:   [B, G*9, H, W] f32

#define BB   4
#define CC_T 256
#define HH   128
#define WW   256
#define GG   4
#define CG   64
#define WIN  9
#define PADW 4
#define CCH  8

__global__ __launch_bounds__(WW, 4)
void crestereo_corr_kernel(const float* __restrict__ left,
                           const float* __restrict__ right,
                           const float* __restrict__ flow,
                           float* __restrict__ out)
{
    __shared__ float sh[CCH][WW];

    // bid = ((b*H + y)*G + g): adjacent-y blocks launch adjacently -> L2 reuse
    const int bid = blockIdx.x;
    const int g   = bid & (GG - 1);
    const int by  = bid >> 2;
    const int y   = by & (HH - 1);
    const int b   = by >> 7;

    const int x = threadIdx.x;

    // ---- per-pixel bilinear sampling parameters (computed once) ----
    const float fx = flow[((b * 2 + 0) * HH + y) * WW + x];
    const float fy = flow[((b * 2 + 1) * HH + y) * WW + x];
    const float sx = (float)x + fx;
    const float sy = (float)y + fy;
    const float x0f = floorf(sx);
    const float y0f = floorf(sy);
    const float axf = sx - x0f;
    const float ayf = sy - y0f;
    const int x0 = (int)x0f, y0 = (int)y0f;
    const int x1 = x0 + 1,   y1 = y0 + 1;

    float w00 = (1.f - axf) * (1.f - ayf);
    float w01 = axf * (1.f - ayf);
    float w10 = (1.f - axf) * ayf;
    float w11 = axf * ayf;

    const bool vx0 = ((unsigned)x0 < (unsigned)WW);
    const bool vx1 = ((unsigned)x1 < (unsigned)WW);
    const bool vy0 = ((unsigned)y0 < (unsigned)HH);
    const bool vy1 = ((unsigned)y1 < (unsigned)HH);
    if (!(vx0 && vy0)) w00 = 0.f;
    if (!(vx1 && vy0)) w01 = 0.f;
    if (!(vx0 && vy1)) w10 = 0.f;
    if (!(vx1 && vy1)) w11 = 0.f;

    const int cx0 = min(max(x0, 0), WW - 1);
    const int cx1 = min(max(x1, 0), WW - 1);
    const int cy0 = min(max(y0, 0), HH - 1);
    const int cy1 = min(max(y1, 0), HH - 1);
    const int o00 = cy0 * WW + cx0;
    const int o01 = cy0 * WW + cx1;
    const int o10 = cy1 * WW + cx0;
    const int o11 = cy1 * WW + cx1;

    const float* __restrict__ rbase = right + ((size_t)(b * CC_T + g * CG)) * (HH * WW);
    const float* __restrict__ lbase = left  + ((size_t)(b * CC_T + g * CG)) * (HH * WW)
                                            + (size_t)y * WW + x;

    // Replicate-pad correlation indices (constant per thread).
    int idxm[WIN];
#pragma unroll
    for (int o = 0; o < WIN; o++) idxm[o] = min(max(x + o - PADW, 0), WW - 1);

    float acc[WIN];
#pragma unroll
    for (int o = 0; o < WIN; o++) acc[o] = 0.f;

    for (int c0 = 0; c0 < CG; c0 += CCH) {
        float vreg[CCH];
        __syncthreads();   // previous chunk's reads complete before overwrite
#pragma unroll
        for (int cc = 0; cc < CCH; cc++) {
            const float* __restrict__ rp = rbase + (size_t)(c0 + cc) * (HH * WW);
            float v = w00 * __ldg(rp + o00) + w01 * __ldg(rp + o01)
                    + w10 * __ldg(rp + o10) + w11 * __ldg(rp + o11);
            vreg[cc]  = v;
            sh[cc][x] = v;
        }
        __syncthreads();
#pragma unroll
        for (int cc = 0; cc < CCH; cc++) {
            const float l = __ldcs(lbase + (size_t)(c0 + cc) * (HH * WW));
#pragma unroll
            for (int o = 0; o < WIN; o++) {
                // center tap (o==PADW) is this thread's own value -> register
                const float wv = (o == PADW) ? vreg[cc] : sh[cc][idxm[o]];
                acc[o] = fmaf(l, wv, acc[o]);
            }
        }
    }

    const float scale = 1.f / (float)CG;
    float* __restrict__ ob = out + (((size_t)(b * GG + g) * WIN) * HH + y) * WW + x;
#pragma unroll
    for (int o = 0; o < WIN; o++)
        __stcs(ob + (size_t)o * HH * WW, acc[o] * scale);
}

extern "C" void kernel_launch(void* const* d_in, const int* in_sizes, int n_in,
                              void* d_out, int out_size)
{
    const float* left  = (const float*)d_in[0];
    const float* right = (const float*)d_in[1];
    const float* flow  = (const float*)d_in[2];
    float* out = (float*)d_out;

    const int grid = BB * HH * GG;   // 2048 CTAs, 256 threads each
    crestereo_corr_kernel<<<grid, WW>>>(left, right, flow, out);
}